// round 1
// baseline (speedup 1.0000x reference)
#include <cuda_runtime.h>

#define NN 8192
#define DH 64
#define BI 32
#define BJ 64
#define TPB 256
#define NCHUNK (NN / BJ)

// ---------------- device scratch (no allocation allowed) ----------------
__device__ float g_Wh[NN * DH];
__device__ float g_x[NN * DH];
__device__ float g_src[NN], g_dst[NN];
__device__ float g_A[NN], g_B[NN], g_C[NN], g_D[NN];

// ---------------- packed f32x2 helpers (Blackwell FFMA2) ----------------
__device__ __forceinline__ unsigned long long pack2(float x, float y) {
    unsigned long long r;
    asm("mov.b64 %0, {%1, %2};" : "=l"(r) : "f"(x), "f"(y));
    return r;
}
__device__ __forceinline__ void unpack2(unsigned long long v, float& x, float& y) {
    asm("mov.b64 {%0, %1}, %2;" : "=f"(x), "=f"(y) : "l"(v));
}
__device__ __forceinline__ unsigned long long ffma2(unsigned long long a,
                                                    unsigned long long b,
                                                    unsigned long long c) {
    unsigned long long d;
    asm("fma.rn.f32x2 %0, %1, %2, %3;" : "=l"(d) : "l"(a), "l"(b), "l"(c));
    return d;
}

// ---------------- prep: Wh = x@W^T + b ; src/dst ; exp factors ----------------
// grid 64 x 128 threads, one node-row per thread.
__global__ void prep_kernel(const float* __restrict__ xa, const float* __restrict__ xb,
                            const float* __restrict__ Wm, const float* __restrict__ bv,
                            const float* __restrict__ av, int use_gx) {
    __shared__ float Ws[DH * DH];
    __shared__ float as_[2 * DH];
    __shared__ float bs[DH];
    int t = threadIdx.x;
    for (int k = t; k < DH * DH; k += 128) Ws[k] = Wm[k];
    if (t < 2 * DH) as_[t] = av[t];
    if (t < DH) bs[t] = bv[t];
    __syncthreads();

    int row = blockIdx.x * 128 + t;
    const float* xr;
    if (use_gx) xr = g_x + (size_t)row * DH;
    else xr = (row < NN / 2) ? xa + (size_t)row * DH
                             : xb + (size_t)(row - NN / 2) * DH;

    float x[DH];
#pragma unroll
    for (int q = 0; q < DH / 4; q++) {
        float4 v = ((const float4*)xr)[q];
        x[4 * q + 0] = v.x; x[4 * q + 1] = v.y; x[4 * q + 2] = v.z; x[4 * q + 3] = v.w;
    }

    float srcv = 0.f, dstv = 0.f;
    float4 buf;
    float* whrow = g_Wh + (size_t)row * DH;
    for (int i = 0; i < DH; i++) {
        float acc = bs[i];
#pragma unroll
        for (int j = 0; j < DH; j++) acc += x[j] * Ws[i * DH + j];
        srcv += acc * as_[i];
        dstv += acc * as_[DH + i];
        ((float*)&buf)[i & 3] = acc;
        if ((i & 3) == 3) ((float4*)whrow)[i >> 2] = buf;
    }
    g_src[row] = srcv;
    g_dst[row] = dstv;
    g_A[row] = expf(srcv);
    g_C[row] = expf(0.2f * srcv);
    g_B[row] = expf(dstv);
    g_D[row] = expf(0.2f * dstv);
}

// ---------------- attention: x_out = relu( softmax(mask(e)) @ Wh ) ----------------
// One CTA per BI=32 rows of i; stream over j in BJ=64 chunks.
// w_ij = adj ? ((src_i+dst_j>0) ? A_i*B_j : C_i*D_j) : 0   (no exp in inner loop)
__global__ void __launch_bounds__(TPB) attn_kernel(const int* __restrict__ adj) {
    __shared__ float wh_s[BJ * DH];     // 16 KB, [k][d]
    __shared__ float w_s[BJ * 34];      // 8.5 KB, [k][i] stride 34 (align + bank-safe)
    __shared__ float dpart[TPB];
    __shared__ float dinv[BI];

    int t = threadIdx.x;
    int i0 = blockIdx.x * BI;

    // phase-A mapping: each thread owns one i-row, 8 k's per chunk
    int i_loc = t >> 3, g = t & 7;
    int irow = i0 + i_loc;
    float s_i = g_src[irow];
    float aA = g_A[irow], cC = g_C[irow];
    float dsum = 0.f;

    // GEMM mapping: 16x16 thread grid -> 2 rows x 4 cols per thread
    int tx = t & 15, ty = t >> 4;
    unsigned long long a00 = 0ull, a01 = 0ull, a10 = 0ull, a11 = 0ull;

    const int4* adjrow = (const int4*)(adj + (size_t)irow * NN);

    int4 adjr[2];
    float4 whr[4];
    // prefetch chunk 0
#pragma unroll
    for (int it = 0; it < 2; it++) adjr[it] = adjrow[g + it * 8];
#pragma unroll
    for (int r = 0; r < 4; r++) whr[r] = ((const float4*)g_Wh)[t + r * TPB];

    for (int c = 0; c < NCHUNK; c++) {
        int j0 = c * BJ;

        // ---- phase A: stage Wh tile + compute weight tile ----
#pragma unroll
        for (int r = 0; r < 4; r++) ((float4*)wh_s)[t + r * TPB] = whr[r];

#pragma unroll
        for (int it = 0; it < 2; it++) {
            int k = g * 4 + it * 32;
            int4 a4 = adjr[it];
            float4 dv  = *(const float4*)(g_dst + j0 + k);
            float4 bv  = *(const float4*)(g_B + j0 + k);
            float4 ddv = *(const float4*)(g_D + j0 + k);
            float w0, w1, w2, w3;
            { float s = s_i + dv.x; float p = s > 0.f ? aA : cC; float q = s > 0.f ? bv.x : ddv.x; w0 = a4.x ? p * q : 0.f; }
            { float s = s_i + dv.y; float p = s > 0.f ? aA : cC; float q = s > 0.f ? bv.y : ddv.y; w1 = a4.y ? p * q : 0.f; }
            { float s = s_i + dv.z; float p = s > 0.f ? aA : cC; float q = s > 0.f ? bv.z : ddv.z; w2 = a4.z ? p * q : 0.f; }
            { float s = s_i + dv.w; float p = s > 0.f ? aA : cC; float q = s > 0.f ? bv.w : ddv.w; w3 = a4.w ? p * q : 0.f; }
            dsum += (w0 + w1) + (w2 + w3);
            w_s[(k + 0) * 34 + i_loc] = w0;
            w_s[(k + 1) * 34 + i_loc] = w1;
            w_s[(k + 2) * 34 + i_loc] = w2;
            w_s[(k + 3) * 34 + i_loc] = w3;
        }
        __syncthreads();

        // ---- prefetch next chunk (LDG latency hides under GEMM) ----
        if (c + 1 < NCHUNK) {
            int j1 = j0 + BJ;
#pragma unroll
            for (int it = 0; it < 2; it++) adjr[it] = adjrow[(j1 >> 2) + g + it * 8];
#pragma unroll
            for (int r = 0; r < 4; r++)
                whr[r] = ((const float4*)g_Wh)[(size_t)j1 * (DH / 4) + t + r * TPB];
        }

        // ---- phase B: C[32x64] += W[32 x BJ] * Wh[BJ x 64] with FFMA2 ----
#pragma unroll 8
        for (int k = 0; k < BJ; k++) {
            float2 wp = *(const float2*)(w_s + k * 34 + ty * 2);
            ulonglong2 h = *(const ulonglong2*)(wh_s + k * DH + tx * 4);
            unsigned long long wq0 = pack2(wp.x, wp.x);
            unsigned long long wq1 = pack2(wp.y, wp.y);
            a00 = ffma2(wq0, h.x, a00);
            a01 = ffma2(wq0, h.y, a01);
            a10 = ffma2(wq1, h.x, a10);
            a11 = ffma2(wq1, h.y, a11);
        }
        __syncthreads();
    }

    // ---- row denominators (softmax normalization) ----
    dpart[t] = dsum;   // t == i_loc*8 + g
    __syncthreads();
    if (t < BI) {
        float d = 0.f;
#pragma unroll
        for (int q = 0; q < 8; q++) d += dpart[t * 8 + q];
        dinv[t] = 1.0f / d;
    }
    __syncthreads();

    float inv0 = dinv[ty * 2], inv1 = dinv[ty * 2 + 1];
    float o0, o1, o2, o3;
    float4 outv;

    unpack2(a00, o0, o1); unpack2(a01, o2, o3);
    outv.x = fmaxf(o0 * inv0, 0.f); outv.y = fmaxf(o1 * inv0, 0.f);
    outv.z = fmaxf(o2 * inv0, 0.f); outv.w = fmaxf(o3 * inv0, 0.f);
    ((float4*)(g_x + (size_t)(i0 + ty * 2) * DH))[tx] = outv;

    unpack2(a10, o0, o1); unpack2(a11, o2, o3);
    outv.x = fmaxf(o0 * inv1, 0.f); outv.y = fmaxf(o1 * inv1, 0.f);
    outv.z = fmaxf(o2 * inv1, 0.f); outv.w = fmaxf(o3 * inv1, 0.f);
    ((float4*)(g_x + (size_t)(i0 + ty * 2 + 1) * DH))[tx] = outv;
}

// ---------------- final: out = x @ out_w^T + out_b ----------------
__global__ void final_kernel(const float* __restrict__ Wm, const float* __restrict__ bv,
                             float* __restrict__ out) {
    __shared__ float Ws[DH * DH];
    __shared__ float bs[DH];
    int t = threadIdx.x;
    for (int k = t; k < DH * DH; k += 128) Ws[k] = Wm[k];
    if (t < DH) bs[t] = bv[t];
    __syncthreads();

    int row = blockIdx.x * 128 + t;
    const float* xr = g_x + (size_t)row * DH;
    float x[DH];
#pragma unroll
    for (int q = 0; q < DH / 4; q++) {
        float4 v = ((const float4*)xr)[q];
        x[4 * q + 0] = v.x; x[4 * q + 1] = v.y; x[4 * q + 2] = v.z; x[4 * q + 3] = v.w;
    }
    float4 buf;
    float* orow = out + (size_t)row * DH;
    for (int i = 0; i < DH; i++) {
        float acc = bs[i];
#pragma unroll
        for (int j = 0; j < DH; j++) acc += x[j] * Ws[i * DH + j];
        ((float*)&buf)[i & 3] = acc;
        if ((i & 3) == 3) ((float4*)orow)[i >> 2] = buf;
    }
}

// ---------------- launch ----------------
extern "C" void kernel_launch(void* const* d_in, const int* in_sizes, int n_in,
                              void* d_out, int out_size) {
    const int*   adj  = (const int*)d_in[0];
    const float* user = (const float*)d_in[1];
    const float* item = (const float*)d_in[2];
    const float* W0   = (const float*)d_in[3];
    const float* b0   = (const float*)d_in[4];
    const float* a0   = (const float*)d_in[5];
    const float* W1   = (const float*)d_in[6];
    const float* b1   = (const float*)d_in[7];
    const float* a1   = (const float*)d_in[8];
    const float* ow   = (const float*)d_in[9];
    const float* ob   = (const float*)d_in[10];

    prep_kernel<<<NN / 128, 128>>>(user, item, W0, b0, a0, 0);
    attn_kernel<<<NN / BI, TPB>>>(adj);
    prep_kernel<<<NN / 128, 128>>>(nullptr, nullptr, W1, b1, a1, 1);
    attn_kernel<<<NN / BI, TPB>>>(adj);
    final_kernel<<<NN / 128, 128>>>(ow, ob, (float*)d_out);
}